// round 10
// baseline (speedup 1.0000x reference)
#include <cuda_runtime.h>
#include <cuda_fp16.h>
#include <cstdint>

#define NB   8
#define SQL  2048
#define SKL  2048
#define HIDN 1024
// NORM = 32 -> alpha = 1/32 (folded into q projection; exact in fp16)

// Scratch (__device__ globals per allocation-free rule). All fp16 GEMM
// operands live in "interleaved-16" layout along their K dimension:
// within each 16-half block, halves are stored [0,1,8,9,2,3,10,11,4,5,12,13,6,7,14,15]
// so that mma.m16n8k16 fragments are contiguous 8B chunks in smem.
__device__ __align__(16) __half g_xq[(size_t)NB * SQL * HIDN];  // query fp16 (ilv)
__device__ __align__(16) __half g_xk[(size_t)NB * SKL * HIDN];  // key   fp16 (ilv)
__device__ __align__(16) __half g_w [(size_t)3 * HIDN * HIDN];  // Wq|Wk|Wv fp16 (ilv)
__device__ __align__(16) __half g_q [(size_t)NB * SQL * HIDN];  // q/32 fp16 (ilv)
__device__ __align__(16) __half g_k [(size_t)NB * SKL * HIDN];  // k fp16 (ilv)
__device__ __align__(16) __half g_vt[(size_t)NB * HIDN * SKL];  // v^T [b][h][sk] fp16 (ilv)
__device__ __align__(16) __half g_p [(size_t)NB * SQL * SKL];   // probs fp16 (ilv)

// logical half index -> physical half index (interleave within 16-block)
__device__ __forceinline__ int ilv16(int k) {
    const int blk = k >> 4, kk = k & 15;
    const int p = kk >> 1, lo = kk & 1;
    const int w = (p < 4) ? (2 * p) : (2 * (p - 4) + 1);
    return blk * 16 + 2 * w + lo;
}

__device__ __forceinline__ void mma16(float* c, unsigned a0, unsigned a1,
                                      unsigned a2, unsigned a3,
                                      unsigned b0, unsigned b1) {
    asm volatile(
        "mma.sync.aligned.m16n8k16.row.col.f32.f16.f16.f32 "
        "{%0,%1,%2,%3}, {%4,%5,%6,%7}, {%8,%9}, {%0,%1,%2,%3};\n"
        : "+f"(c[0]), "+f"(c[1]), "+f"(c[2]), "+f"(c[3])
        : "r"(a0), "r"(a1), "r"(a2), "r"(a3), "r"(b0), "r"(b1));
}

__device__ __forceinline__ void cpa16(void* dst, const void* src) {
    unsigned d = (unsigned)__cvta_generic_to_shared(dst);
    asm volatile("cp.async.cg.shared.global [%0], [%1], 16;" :: "r"(d), "l"(src) : "memory");
}
__device__ __forceinline__ void cp_commit() { asm volatile("cp.async.commit_group;"); }
__device__ __forceinline__ void cp_wait1()  { asm volatile("cp.async.wait_group 1;"); }
__device__ __forceinline__ void cp_wait0()  { asm volatile("cp.async.wait_group 0;"); }

// ---------------------------------------------------------------------------
// GEMM core: C[m,n] = sum_k A[m,k]*B[n,k]; A,B fp16 interleaved-16 layout.
// 128x128 CTA tile, BK=64 per sync (four independent 16-K sub-tiles, proven
// 128x16 / 32B-row smem layout each). 8 warps, warp tile 32x64.
// 3-stage cp.async ring (3 x 32KB dynamic smem), 1 syncthreads per 64-K iter.
// K, N compile-time -> full constant folding of stage offsets (outer loop in
// steps of 3 with unrolled j so every stage index is a literal).
//   MODE 0: C(half) = half((acc + bias[n]) * alpha), interleaved col store
//   MODE 2: C(f32)  = acc; mask==0 -> -inf   (alpha pre-folded into A)
//   MODE 3: C(f32)  = acc
//   MODE 4: vt[b][h][sk] = half(acc + bias[n]) transposed via smem, ilv16 sk
// ---------------------------------------------------------------------------
template<int MODE, int K, int N>
__device__ __forceinline__ void gemm_core(
    const __half* __restrict__ A, const __half* __restrict__ B,
    const float* __restrict__ bias, const int* __restrict__ mask,
    void* __restrict__ Cout, float alpha)
{
    extern __shared__ __align__(16) char sm[];   // 3 stages x [A 16KB | B 16KB]

    const int m0 = blockIdx.y * 128, n0 = blockIdx.x * 128;
    const int t = threadIdx.x, lane = t & 31, warp = t >> 5;
    const int wm = (warp & 3) * 32, wn = (warp >> 2) * 64;
    const int g = lane >> 2, tg = lane & 3;

    // producer mapping: thread -> row (t>>1); lane-pairs cover one aligned
    // 32B sector per cp.async instruction.
    const int prow = t >> 1, ph = t & 1;
    const __half* pA = A + (long)(m0 + prow) * K + ph * 8;
    const __half* pB = B + (long)(n0 + prow) * K + ph * 8;
    const int soff = prow * 32 + ph * 16;     // bytes within a 4KB sub-tile

    float acc[2][8][4];
    #pragma unroll
    for (int i = 0; i < 2; i++)
        #pragma unroll
        for (int j = 0; j < 8; j++)
            #pragma unroll
            for (int l = 0; l < 4; l++) acc[i][j][l] = 0.f;

    auto load_stage = [&](int st, int kt) {   // kt indexes 64-K stages
        char* base = sm + st * 32768;
        const long ko = (long)kt * 64;
        #pragma unroll
        for (int s = 0; s < 4; s++) {         // sub-tile s covers k [16s,16s+16)
            cpa16(base +         s * 4096 + soff, pA + ko + s * 16);
            cpa16(base + 16384 + s * 4096 + soff, pB + ko + s * 16);
        }
    };
    auto comp16 = [&](const char* As, const char* Bs) {
        uint2 bf[8];
        #pragma unroll
        for (int nt = 0; nt < 8; nt++)
            bf[nt] = *(const uint2*)(Bs + (wn + nt * 8 + g) * 32 + tg * 8);
        #pragma unroll
        for (int mt = 0; mt < 2; mt++) {
            const int r = wm + mt * 16 + g;
            const uint2 pa = *(const uint2*)(As + r * 32 + tg * 8);
            const uint2 pb = *(const uint2*)(As + (r + 8) * 32 + tg * 8);
            #pragma unroll
            for (int nt = 0; nt < 8; nt++)
                mma16(acc[mt][nt], pa.x, pb.x, pa.y, pb.y, bf[nt].x, bf[nt].y);
        }
    };
    auto comp = [&](int st) {
        const char* base = sm + st * 32768;
        #pragma unroll
        for (int s = 0; s < 4; s++)
            comp16(base + s * 4096, base + 16384 + s * 4096);
    };

    constexpr int nK = K >> 6;                // 64-K stages (16 or 32)
    load_stage(0, 0); cp_commit();
    load_stage(1, 1); cp_commit();
    cp_wait1();
    __syncthreads();

    // outer step of 3 -> stage index inside is the literal j (kt % 3 == j)
    for (int base = 0; base < nK; base += 3) {
        #pragma unroll
        for (int j = 0; j < 3; j++) {
            const int kt = base + j;
            if (kt >= nK) break;
            comp(j);
            if (kt + 2 < nK) {
                load_stage((j + 2) % 3, kt + 2);
                cp_commit();
                cp_wait1();
            } else {
                cp_wait0();
            }
            __syncthreads();
        }
    }

    // ---------------- epilogues ----------------
    const float NEG = __int_as_float(0xff800000);
    if (MODE == 4) {
        // transposed store to vt via smem (mainloop smem is dead now)
        __half* T = (__half*)sm;
        constexpr int LDT = 138;              // halves per row; conflict-tuned
        #pragma unroll
        for (int mt = 0; mt < 2; mt++) {
            #pragma unroll
            for (int nt = 0; nt < 8; nt++) {
                const int rl = wm + mt * 16 + g;      // local row (sk)
                const int cl = wn + nt * 8 + tg * 2;  // local col (h)
                const float2 bb = *(const float2*)&bias[n0 + cl];
                float* c = acc[mt][nt];
                T[(cl    ) * LDT + rl    ] = __float2half_rn(c[0] + bb.x);
                T[(cl + 1) * LDT + rl    ] = __float2half_rn(c[1] + bb.y);
                T[(cl    ) * LDT + rl + 8] = __float2half_rn(c[2] + bb.x);
                T[(cl + 1) * LDT + rl + 8] = __float2half_rn(c[3] + bb.y);
            }
        }
        __syncthreads();
        const int b_  = m0 >> 11;             // batch  (M rows = b*2048 + sk)
        const int sk0 = m0 & 2047;
        const int hl  = t >> 1;               // local h row 0..127
        const int seg = (t & 1) * 64;         // half of the 128-sk row
        __half* dst = (__half*)Cout + ((long)b_ * HIDN + n0 + hl) * SKL + sk0 + seg;
        const __half* src = T + hl * LDT + seg;
        #pragma unroll
        for (int bk = 0; bk < 4; bk++) {      // 4 x 16-half blocks
            const unsigned* s = (const unsigned*)(src + bk * 16);
            const uint4 w0 = make_uint4(s[0], s[4], s[1], s[5]);  // ilv16 word order
            const uint4 w1 = make_uint4(s[2], s[6], s[3], s[7]);
            ((uint4*)dst)[bk * 2    ] = w0;
            ((uint4*)dst)[bk * 2 + 1] = w1;
        }
        return;
    }

    #pragma unroll
    for (int mt = 0; mt < 2; mt++) {
        #pragma unroll
        for (int nt = 0; nt < 8; nt++) {
            const int row = m0 + wm + mt * 16 + g;
            const int col = n0 + wn + nt * 8 + tg * 2;
            float* c = acc[mt][nt];
            if (MODE == 0) {
                __half* C = (__half*)Cout;
                const float2 bb = *(const float2*)&bias[col];
                const __half2 h0 = __floats2half2_rn((c[0] + bb.x) * alpha,
                                                     (c[1] + bb.y) * alpha);
                const __half2 h1 = __floats2half2_rn((c[2] + bb.x) * alpha,
                                                     (c[3] + bb.y) * alpha);
                const int cc = ilv16(col);
                *(__half2*)&C[(long)row       * N + cc] = h0;
                *(__half2*)&C[(long)(row + 8) * N + cc] = h1;
            } else if (MODE == 2) {
                float* C = (float*)Cout;
                const long r0 = (long)row * N + col;
                const long r1 = (long)(row + 8) * N + col;
                const int2 mv0 = *(const int2*)&mask[r0];
                const int2 mv1 = *(const int2*)&mask[r1];
                *(float2*)&C[r0] = make_float2(mv0.x ? c[0] : NEG, mv0.y ? c[1] : NEG);
                *(float2*)&C[r1] = make_float2(mv1.x ? c[2] : NEG, mv1.y ? c[3] : NEG);
            } else {
                float* C = (float*)Cout;
                *(float2*)&C[(long)row       * N + col] = make_float2(c[0], c[1]);
                *(float2*)&C[(long)(row + 8) * N + col] = make_float2(c[2], c[3]);
            }
        }
    }
}

// Batched fp32-out GEMM (score MODE 2 / output MODE 3), z = batch.
template<int MODE, int K, int N>
__launch_bounds__(256, 2)
__global__ void hgemm(const __half* __restrict__ Ag, const __half* __restrict__ Bg,
                      const int* __restrict__ mask, float* __restrict__ Cg,
                      long sA, long sB, long sC)
{
    const int bz = blockIdx.z;
    gemm_core<MODE, K, N>(Ag + (long)bz * sA, Bg + (long)bz * sB, nullptr,
                          (MODE == 2) ? (mask + (long)bz * sC) : nullptr,
                          Cg + (long)bz * sC, 1.0f);
}

// Fused QKV projection: z=0 -> q/32 (ilv), z=1 -> k (ilv), z=2 -> vt (transposed).
__launch_bounds__(256, 2)
__global__ void proj3(const __half* __restrict__ xq, const __half* __restrict__ xk,
                      const __half* __restrict__ w,
                      const float* __restrict__ bq, const float* __restrict__ bk,
                      const float* __restrict__ bv,
                      __half* __restrict__ q, __half* __restrict__ k,
                      __half* __restrict__ vt)
{
    const int z = blockIdx.z;
    if (z == 0)
        gemm_core<0, HIDN, HIDN>(xq, w, bq, nullptr, q, 0.03125f);
    else if (z == 1)
        gemm_core<0, HIDN, HIDN>(xk, w + (long)HIDN * HIDN, bk, nullptr, k, 1.0f);
    else
        gemm_core<4, HIDN, HIDN>(xk, w + 2L * HIDN * HIDN, bv, nullptr, vt, 1.0f);
}

// ---------------------------------------------------------------------------
// fp32 -> fp16 with interleave-16 permutation. One thread per 16-half block.
// ---------------------------------------------------------------------------
__device__ __forceinline__ void f2h_blk(const float* __restrict__ in,
                                        __half* __restrict__ outp, long i)
{
    const float4 f0 = ((const float4*)in)[i * 4 + 0];
    const float4 f1 = ((const float4*)in)[i * 4 + 1];
    const float4 f2 = ((const float4*)in)[i * 4 + 2];
    const float4 f3 = ((const float4*)in)[i * 4 + 3];
    // phys word order: k(0,1) k(8,9) k(2,3) k(10,11) k(4,5) k(12,13) k(6,7) k(14,15)
    __half2 w[8];
    w[0] = __floats2half2_rn(f0.x, f0.y);
    w[1] = __floats2half2_rn(f2.x, f2.y);
    w[2] = __floats2half2_rn(f0.z, f0.w);
    w[3] = __floats2half2_rn(f2.z, f2.w);
    w[4] = __floats2half2_rn(f1.x, f1.y);
    w[5] = __floats2half2_rn(f3.x, f3.y);
    w[6] = __floats2half2_rn(f1.z, f1.w);
    w[7] = __floats2half2_rn(f3.z, f3.w);
    uint4* dst = (uint4*)(outp + i * 16);
    dst[0] = *(uint4*)&w[0];
    dst[1] = *(uint4*)&w[4];
}

// query+key fused convert: z=0 -> query->xq, z=1 -> key->xk
__global__ void f2h_qk(const float* __restrict__ query, const float* __restrict__ key,
                       __half* __restrict__ xq, __half* __restrict__ xk, long nblk)
{
    const long i = blockIdx.x * (long)blockDim.x + threadIdx.x;
    if (i >= nblk) return;
    if (blockIdx.z == 0) f2h_blk(query, xq, i);
    else                 f2h_blk(key,   xk, i);
}

// 3-weight fused convert: z selects Wq/Wk/Wv -> w + z*H*H
__global__ void f2h_w(const float* __restrict__ Wq, const float* __restrict__ Wk,
                      const float* __restrict__ Wv, __half* __restrict__ w, long nblk)
{
    const long i = blockIdx.x * (long)blockDim.x + threadIdx.x;
    if (i >= nblk) return;
    const int z = blockIdx.z;
    const float* in = (z == 0) ? Wq : (z == 1) ? Wk : Wv;
    f2h_blk(in, w + (long)z * HIDN * HIDN, i);
}

// ---------------------------------------------------------------------------
// Row softmax over SK=2048; -inf mask; fully-masked row -> zeros.
// In-place fp32 S + interleaved fp16 copy P.
// ---------------------------------------------------------------------------
__device__ __forceinline__ float warpRedMax(float v) {
    #pragma unroll
    for (int o = 16; o > 0; o >>= 1) v = fmaxf(v, __shfl_xor_sync(0xffffffffu, v, o));
    return v;
}
__device__ __forceinline__ float warpRedSum(float v) {
    #pragma unroll
    for (int o = 16; o > 0; o >>= 1) v += __shfl_xor_sync(0xffffffffu, v, o);
    return v;
}

__global__ void softmax_k(float* __restrict__ S, __half* __restrict__ P) {
    const long row = blockIdx.x;
    float4* p4 = (float4*)(S + row * (long)SKL);
    __half* pr = P + row * (long)SKL;
    const int t = threadIdx.x;
    __shared__ float red[8];

    float4 v0 = p4[t], v1 = p4[t + 256];
    float m = fmaxf(fmaxf(fmaxf(v0.x, v0.y), fmaxf(v0.z, v0.w)),
                    fmaxf(fmaxf(v1.x, v1.y), fmaxf(v1.z, v1.w)));
    m = warpRedMax(m);
    if ((t & 31) == 0) red[t >> 5] = m;
    __syncthreads();
    m = red[0];
    #pragma unroll
    for (int i = 1; i < 8; i++) m = fmaxf(m, red[i]);
    __syncthreads();

    const int k0 = t * 4, k1 = 1024 + t * 4;
    if (m == __int_as_float(0xff800000)) {
        const float4 z = make_float4(0.f, 0.f, 0.f, 0.f);
        p4[t] = z; p4[t + 256] = z;
        const __half2 hz = __floats2half2_rn(0.f, 0.f);
        *(__half2*)&pr[ilv16(k0)]     = hz;
        *(__half2*)&pr[ilv16(k0 + 2)] = hz;
        *(__half2*)&pr[ilv16(k1)]     = hz;
        *(__half2*)&pr[ilv16(k1 + 2)] = hz;
        return;
    }

    v0.x = __expf(v0.x - m); v0.y = __expf(v0.y - m);
    v0.z = __expf(v0.z - m); v0.w = __expf(v0.w - m);
    v1.x = __expf(v1.x - m); v1.y = __expf(v1.y - m);
    v1.z = __expf(v1.z - m); v1.w = __expf(v1.w - m);

    float s = v0.x + v0.y + v0.z + v0.w + v1.x + v1.y + v1.z + v1.w;
    s = warpRedSum(s);
    if ((t & 31) == 0) red[t >> 5] = s;
    __syncthreads();
    s = red[0];
    #pragma unroll
    for (int i = 1; i < 8; i++) s += red[i];

    const float inv = 1.0f / s;
    v0.x *= inv; v0.y *= inv; v0.z *= inv; v0.w *= inv;
    v1.x *= inv; v1.y *= inv; v1.z *= inv; v1.w *= inv;
    p4[t] = v0; p4[t + 256] = v1;

    *(__half2*)&pr[ilv16(k0)]     = __floats2half2_rn(v0.x, v0.y);
    *(__half2*)&pr[ilv16(k0 + 2)] = __floats2half2_rn(v0.z, v0.w);
    *(__half2*)&pr[ilv16(k1)]     = __floats2half2_rn(v1.x, v1.y);
    *(__half2*)&pr[ilv16(k1 + 2)] = __floats2half2_rn(v1.z, v1.w);
}

// ---------------------------------------------------------------------------
extern "C" void kernel_launch(void* const* d_in, const int* in_sizes, int n_in,
                              void* d_out, int out_size)
{
    const float* key   = (const float*)d_in[0];
    const float* query = (const float*)d_in[1];
    const int*   mask  = (const int*)  d_in[2];
    const float* Wq    = (const float*)d_in[3];
    const float* bq    = (const float*)d_in[4];
    const float* Wk    = (const float*)d_in[5];
    const float* bk    = (const float*)d_in[6];
    const float* Wv    = (const float*)d_in[7];
    const float* bv    = (const float*)d_in[8];

    float* out   = (float*)d_out;
    float* score = out + (long)NB * SQL * HIDN;

    __half *xq, *xk, *w, *q, *k, *vt, *p;
    cudaGetSymbolAddress((void**)&xq, g_xq);
    cudaGetSymbolAddress((void**)&xk, g_xk);
    cudaGetSymbolAddress((void**)&w,  g_w);
    cudaGetSymbolAddress((void**)&q,  g_q);
    cudaGetSymbolAddress((void**)&k,  g_k);
    cudaGetSymbolAddress((void**)&vt, g_vt);
    cudaGetSymbolAddress((void**)&p,  g_p);

    const int SMEM = 3 * 32768;   // 96KB
    cudaFuncSetAttribute((const void*)proj3,
                         cudaFuncAttributeMaxDynamicSharedMemorySize, SMEM);
    cudaFuncSetAttribute((const void*)hgemm<2, HIDN, SKL>,
                         cudaFuncAttributeMaxDynamicSharedMemorySize, SMEM);
    cudaFuncSetAttribute((const void*)hgemm<3, SKL, HIDN>,
                         cudaFuncAttributeMaxDynamicSharedMemorySize, SMEM);

    dim3 blk(256);

    // fp16 conversions (interleaved-16 along K), fused launches
    const long nbqk = (long)NB * SQL * HIDN / 16;   // 524288 blocks
    const long nbw  = (long)HIDN * HIDN / 16;       // 65536
    dim3 gqk((unsigned)((nbqk + 255) / 256), 1, 2);
    dim3 gw ((unsigned)((nbw + 255) / 256), 1, 3);
    f2h_qk<<<gqk, blk>>>(query, key, xq, xk, nbqk);
    f2h_w <<<gw,  blk>>>(Wq, Wk, Wv, w, nbw);

    // Fused QKV projections: one launch, z in {q/32, k, vt}
    dim3 gp(HIDN / 128, (NB * SQL) / 128, 3);
    proj3<<<gp, blk, SMEM>>>(xq, xk, w, bq, bk, bv, q, k, vt);

    // Scores: per batch S = (q/32) K^T, mask -> -inf   (fp32 out)
    dim3 gs(SKL / 128, SQL / 128, NB);
    hgemm<2, HIDN, SKL><<<gs, blk, SMEM>>>(q, k, mask, score,
                                           (long)SQL * HIDN, (long)SKL * HIDN,
                                           (long)SQL * SKL);

    // Softmax in place + interleaved fp16 copy to g_p
    softmax_k<<<NB * SQL, 256>>>(score, p);

    // Output: per batch O = P @ V  (NT vs vt[b][h][sk])   fp32 out
    dim3 go(HIDN / 128, SQL / 128, NB);
    hgemm<3, SKL, HIDN><<<go, blk, SMEM>>>(p, vt, nullptr, out,
                                           (long)SQL * SKL, (long)HIDN * SKL,
                                           (long)SQL * HIDN);
}

// round 11
// speedup vs baseline: 1.0319x; 1.0319x over previous
#include <cuda_runtime.h>
#include <cuda_fp16.h>
#include <cstdint>

#define NB   8
#define SQL  2048
#define SKL  2048
#define HIDN 1024
// NORM = 32 -> alpha = 1/32 (folded into q projection; exact in fp16)

// Scratch (__device__ globals per allocation-free rule). All fp16 GEMM
// operands live in "interleaved-16" layout along their K dimension:
// within each 16-half block, halves are stored [0,1,8,9,2,3,10,11,4,5,12,13,6,7,14,15]
// so that mma.m16n8k16 fragments are contiguous 8B chunks in smem.
__device__ __align__(16) __half g_xq[(size_t)NB * SQL * HIDN];  // query fp16 (ilv)
__device__ __align__(16) __half g_xk[(size_t)NB * SKL * HIDN];  // key   fp16 (ilv)
__device__ __align__(16) __half g_w [(size_t)3 * HIDN * HIDN];  // Wq|Wk|Wv fp16 (ilv)
__device__ __align__(16) __half g_q [(size_t)NB * SQL * HIDN];  // q/32 fp16 (ilv)
__device__ __align__(16) __half g_k [(size_t)NB * SKL * HIDN];  // k fp16 (ilv)
__device__ __align__(16) __half g_v [(size_t)NB * SKL * HIDN];  // v fp16 (PLAIN)
__device__ __align__(16) __half g_vt[(size_t)NB * HIDN * SKL];  // v^T [b][h][sk] fp16 (ilv)
__device__ __align__(16) __half g_p [(size_t)NB * SQL * SKL];   // probs fp16 (ilv)

// logical half index -> physical half index (interleave within 16-block)
__device__ __forceinline__ int ilv16(int k) {
    const int blk = k >> 4, kk = k & 15;
    const int p = kk >> 1, lo = kk & 1;
    const int w = (p < 4) ? (2 * p) : (2 * (p - 4) + 1);
    return blk * 16 + 2 * w + lo;
}

__device__ __forceinline__ void mma16(float* c, unsigned a0, unsigned a1,
                                      unsigned a2, unsigned a3,
                                      unsigned b0, unsigned b1) {
    asm volatile(
        "mma.sync.aligned.m16n8k16.row.col.f32.f16.f16.f32 "
        "{%0,%1,%2,%3}, {%4,%5,%6,%7}, {%8,%9}, {%0,%1,%2,%3};\n"
        : "+f"(c[0]), "+f"(c[1]), "+f"(c[2]), "+f"(c[3])
        : "r"(a0), "r"(a1), "r"(a2), "r"(a3), "r"(b0), "r"(b1));
}

__device__ __forceinline__ void cpa16(void* dst, const void* src) {
    unsigned d = (unsigned)__cvta_generic_to_shared(dst);
    asm volatile("cp.async.cg.shared.global [%0], [%1], 16;" :: "r"(d), "l"(src) : "memory");
}
__device__ __forceinline__ void cp_commit() { asm volatile("cp.async.commit_group;"); }
__device__ __forceinline__ void cp_wait1()  { asm volatile("cp.async.wait_group 1;"); }
__device__ __forceinline__ void cp_wait0()  { asm volatile("cp.async.wait_group 0;"); }

// ---------------------------------------------------------------------------
// GEMM core: C[m,n] = sum_k A[m,k]*B[n,k]; A,B fp16 interleaved-16 layout.
// 128x128 CTA tile, BK=64 per sync (four independent 16-K sub-tiles, proven
// 128x16 / 32B-row smem layout each). 8 warps, warp tile 32x64.
// 3-stage cp.async ring (3 x 32KB dynamic smem), rotating stage index
// (PROVEN R7 loop), 1 syncthreads per 64-K iteration. K,N compile-time.
//   MODE 0: C(half) = half((acc + bias[n]) * alpha); il!=0 -> ilv col store
//   MODE 2: C(f32)  = acc; mask==0 -> -inf   (alpha pre-folded into A)
//   MODE 3: C(f32)  = acc
// ---------------------------------------------------------------------------
template<int MODE, int K, int N>
__device__ __forceinline__ void gemm_core(
    const __half* __restrict__ A, const __half* __restrict__ B,
    const float* __restrict__ bias, const int* __restrict__ mask,
    void* __restrict__ Cout, float alpha, int il)
{
    extern __shared__ __align__(16) char sm[];   // 3 stages x [A 16KB | B 16KB]

    const int m0 = blockIdx.y * 128, n0 = blockIdx.x * 128;
    const int t = threadIdx.x, lane = t & 31, warp = t >> 5;
    const int wm = (warp & 3) * 32, wn = (warp >> 2) * 64;
    const int g = lane >> 2, tg = lane & 3;

    // producer mapping: thread -> row (t>>1); lane-pairs cover one aligned
    // 32B sector per cp.async instruction.
    const int prow = t >> 1, ph = t & 1;
    const __half* pA = A + (long)(m0 + prow) * K + ph * 8;
    const __half* pB = B + (long)(n0 + prow) * K + ph * 8;
    const int soff = prow * 32 + ph * 16;     // bytes within a 4KB sub-tile

    float acc[2][8][4];
    #pragma unroll
    for (int i = 0; i < 2; i++)
        #pragma unroll
        for (int j = 0; j < 8; j++)
            #pragma unroll
            for (int l = 0; l < 4; l++) acc[i][j][l] = 0.f;

    auto load_stage = [&](int st, int kt) {   // kt indexes 64-K stages
        char* base = sm + st * 32768;
        const long ko = (long)kt * 64;
        #pragma unroll
        for (int s = 0; s < 4; s++) {         // sub-tile s covers k [16s,16s+16)
            cpa16(base +         s * 4096 + soff, pA + ko + s * 16);
            cpa16(base + 16384 + s * 4096 + soff, pB + ko + s * 16);
        }
    };
    auto comp16 = [&](const char* As, const char* Bs) {
        uint2 bf[8];
        #pragma unroll
        for (int nt = 0; nt < 8; nt++)
            bf[nt] = *(const uint2*)(Bs + (wn + nt * 8 + g) * 32 + tg * 8);
        #pragma unroll
        for (int mt = 0; mt < 2; mt++) {
            const int r = wm + mt * 16 + g;
            const uint2 pa = *(const uint2*)(As + r * 32 + tg * 8);
            const uint2 pb = *(const uint2*)(As + (r + 8) * 32 + tg * 8);
            #pragma unroll
            for (int nt = 0; nt < 8; nt++)
                mma16(acc[mt][nt], pa.x, pb.x, pa.y, pb.y, bf[nt].x, bf[nt].y);
        }
    };
    auto comp = [&](int st) {
        const char* base = sm + st * 32768;
        #pragma unroll
        for (int s = 0; s < 4; s++)
            comp16(base + s * 4096, base + 16384 + s * 4096);
    };

    constexpr int nK = K >> 6;                // 64-K stages (16 or 32)
    load_stage(0, 0); cp_commit();
    load_stage(1, 1); cp_commit();
    cp_wait1();
    __syncthreads();

    int st = 0;
    for (int kt = 0; kt < nK; kt++) {
        comp(st);
        if (kt + 2 < nK) {
            int st2 = st + 2; if (st2 >= 3) st2 -= 3;
            load_stage(st2, kt + 2);
            cp_commit();
            cp_wait1();
        } else {
            cp_wait0();
        }
        __syncthreads();
        if (++st == 3) st = 0;
    }

    // epilogue
    const float NEG = __int_as_float(0xff800000);
    #pragma unroll
    for (int mt = 0; mt < 2; mt++) {
        #pragma unroll
        for (int nt = 0; nt < 8; nt++) {
            const int row = m0 + wm + mt * 16 + g;
            const int col = n0 + wn + nt * 8 + tg * 2;
            float* c = acc[mt][nt];
            if (MODE == 0) {
                __half* C = (__half*)Cout;
                const float2 bb = *(const float2*)&bias[col];
                const __half2 h0 = __floats2half2_rn((c[0] + bb.x) * alpha,
                                                     (c[1] + bb.y) * alpha);
                const __half2 h1 = __floats2half2_rn((c[2] + bb.x) * alpha,
                                                     (c[3] + bb.y) * alpha);
                const int cc = il ? ilv16(col) : col;
                *(__half2*)&C[(long)row       * N + cc] = h0;
                *(__half2*)&C[(long)(row + 8) * N + cc] = h1;
            } else if (MODE == 2) {
                float* C = (float*)Cout;
                const long r0 = (long)row * N + col;
                const long r1 = (long)(row + 8) * N + col;
                const int2 mv0 = *(const int2*)&mask[r0];
                const int2 mv1 = *(const int2*)&mask[r1];
                *(float2*)&C[r0] = make_float2(mv0.x ? c[0] : NEG, mv0.y ? c[1] : NEG);
                *(float2*)&C[r1] = make_float2(mv1.x ? c[2] : NEG, mv1.y ? c[3] : NEG);
            } else {
                float* C = (float*)Cout;
                *(float2*)&C[(long)row       * N + col] = make_float2(c[0], c[1]);
                *(float2*)&C[(long)(row + 8) * N + col] = make_float2(c[2], c[3]);
            }
        }
    }
}

// Batched fp32-out GEMM (score MODE 2 / output MODE 3), z = batch.
template<int MODE, int K, int N>
__launch_bounds__(256, 2)
__global__ void hgemm(const __half* __restrict__ Ag, const __half* __restrict__ Bg,
                      const int* __restrict__ mask, float* __restrict__ Cg,
                      long sA, long sB, long sC)
{
    const int bz = blockIdx.z;
    gemm_core<MODE, K, N>(Ag + (long)bz * sA, Bg + (long)bz * sB, nullptr,
                          (MODE == 2) ? (mask + (long)bz * sC) : nullptr,
                          Cg + (long)bz * sC, 1.0f, 0);
}

// Fused QKV projection: z=0 -> q/32 (ilv), z=1 -> k (ilv), z=2 -> v (plain).
__launch_bounds__(256, 2)
__global__ void proj3(const __half* __restrict__ xq, const __half* __restrict__ xk,
                      const __half* __restrict__ w,
                      const float* __restrict__ bq, const float* __restrict__ bk,
                      const float* __restrict__ bv,
                      __half* __restrict__ q, __half* __restrict__ k,
                      __half* __restrict__ v)
{
    const int z = blockIdx.z;
    const __half* A = (z == 0) ? xq : xk;
    const __half* B = w + (long)z * HIDN * HIDN;
    const float* bias = (z == 0) ? bq : (z == 1) ? bk : bv;
    __half* C = (z == 0) ? q : (z == 1) ? k : v;
    const float alpha = (z == 0) ? 0.03125f : 1.0f;
    gemm_core<0, HIDN, HIDN>(A, B, bias, nullptr, C, alpha, (z < 2) ? 1 : 0);
}

// ---------------------------------------------------------------------------
// fp32 -> fp16 with interleave-16 permutation. One thread per 16-half block.
// ---------------------------------------------------------------------------
__device__ __forceinline__ void f2h_blk(const float* __restrict__ in,
                                        __half* __restrict__ outp, long i)
{
    const float4 f0 = ((const float4*)in)[i * 4 + 0];
    const float4 f1 = ((const float4*)in)[i * 4 + 1];
    const float4 f2 = ((const float4*)in)[i * 4 + 2];
    const float4 f3 = ((const float4*)in)[i * 4 + 3];
    // phys word order: k(0,1) k(8,9) k(2,3) k(10,11) k(4,5) k(12,13) k(6,7) k(14,15)
    __half2 w[8];
    w[0] = __floats2half2_rn(f0.x, f0.y);
    w[1] = __floats2half2_rn(f2.x, f2.y);
    w[2] = __floats2half2_rn(f0.z, f0.w);
    w[3] = __floats2half2_rn(f2.z, f2.w);
    w[4] = __floats2half2_rn(f1.x, f1.y);
    w[5] = __floats2half2_rn(f3.x, f3.y);
    w[6] = __floats2half2_rn(f1.z, f1.w);
    w[7] = __floats2half2_rn(f3.z, f3.w);
    uint4* dst = (uint4*)(outp + i * 16);
    dst[0] = *(uint4*)&w[0];
    dst[1] = *(uint4*)&w[4];
}

// query+key fused convert: z=0 -> query->xq, z=1 -> key->xk
__global__ void f2h_qk(const float* __restrict__ query, const float* __restrict__ key,
                       __half* __restrict__ xq, __half* __restrict__ xk, long nblk)
{
    const long i = blockIdx.x * (long)blockDim.x + threadIdx.x;
    if (i >= nblk) return;
    if (blockIdx.z == 0) f2h_blk(query, xq, i);
    else                 f2h_blk(key,   xk, i);
}

// 3-weight fused convert: z selects Wq/Wk/Wv -> w + z*H*H
__global__ void f2h_w(const float* __restrict__ Wq, const float* __restrict__ Wk,
                      const float* __restrict__ Wv, __half* __restrict__ w, long nblk)
{
    const long i = blockIdx.x * (long)blockDim.x + threadIdx.x;
    if (i >= nblk) return;
    const int z = blockIdx.z;
    const float* in = (z == 0) ? Wq : (z == 1) ? Wk : Wv;
    f2h_blk(in, w + (long)z * HIDN * HIDN, i);
}

// ---------------------------------------------------------------------------
// V transpose (per batch): v[b][sk][h] plain fp16 -> vt[b][h][sk] ilv fp16.
// 64x64 tiles, 256 threads.
// ---------------------------------------------------------------------------
__global__ void vtrans_k(const __half* __restrict__ v, __half* __restrict__ vt)
{
    __shared__ __half tile[64][66];
    const int b = blockIdx.z;
    const int h0 = blockIdx.x * 64, sk0 = blockIdx.y * 64;
    const int t = threadIdx.x;

    const __half* src = v + ((long)b * SKL + sk0) * HIDN + h0;
    #pragma unroll
    for (int kx = 0; kx < 8; kx++) {
        const int id = t + kx * 256;
        const int r = id >> 5, c2 = id & 31;
        *(__half2*)&tile[r][c2 * 2] = *(const __half2*)&src[(long)r * HIDN + c2 * 2];
    }
    __syncthreads();
    __half* dst = vt + ((long)b * HIDN + h0) * SKL;
    #pragma unroll
    for (int kx = 0; kx < 8; kx++) {
        const int id = t + kx * 256;
        const int r = id >> 5, c2 = id & 31;
        const __half2 o = __halves2half2(tile[c2 * 2][r], tile[c2 * 2 + 1][r]);
        *(__half2*)&dst[(long)r * SKL + ilv16(sk0 + c2 * 2)] = o;
    }
}

// ---------------------------------------------------------------------------
// Row softmax over SK=2048; -inf mask; fully-masked row -> zeros.
// In-place fp32 S + interleaved fp16 copy P.
// ---------------------------------------------------------------------------
__device__ __forceinline__ float warpRedMax(float v) {
    #pragma unroll
    for (int o = 16; o > 0; o >>= 1) v = fmaxf(v, __shfl_xor_sync(0xffffffffu, v, o));
    return v;
}
__device__ __forceinline__ float warpRedSum(float v) {
    #pragma unroll
    for (int o = 16; o > 0; o >>= 1) v += __shfl_xor_sync(0xffffffffu, v, o);
    return v;
}

__global__ void softmax_k(float* __restrict__ S, __half* __restrict__ P) {
    const long row = blockIdx.x;
    float4* p4 = (float4*)(S + row * (long)SKL);
    __half* pr = P + row * (long)SKL;
    const int t = threadIdx.x;
    __shared__ float red[8];

    float4 v0 = p4[t], v1 = p4[t + 256];
    float m = fmaxf(fmaxf(fmaxf(v0.x, v0.y), fmaxf(v0.z, v0.w)),
                    fmaxf(fmaxf(v1.x, v1.y), fmaxf(v1.z, v1.w)));
    m = warpRedMax(m);
    if ((t & 31) == 0) red[t >> 5] = m;
    __syncthreads();
    m = red[0];
    #pragma unroll
    for (int i = 1; i < 8; i++) m = fmaxf(m, red[i]);
    __syncthreads();

    const int k0 = t * 4, k1 = 1024 + t * 4;
    if (m == __int_as_float(0xff800000)) {
        const float4 z = make_float4(0.f, 0.f, 0.f, 0.f);
        p4[t] = z; p4[t + 256] = z;
        const __half2 hz = __floats2half2_rn(0.f, 0.f);
        *(__half2*)&pr[ilv16(k0)]     = hz;
        *(__half2*)&pr[ilv16(k0 + 2)] = hz;
        *(__half2*)&pr[ilv16(k1)]     = hz;
        *(__half2*)&pr[ilv16(k1 + 2)] = hz;
        return;
    }

    v0.x = __expf(v0.x - m); v0.y = __expf(v0.y - m);
    v0.z = __expf(v0.z - m); v0.w = __expf(v0.w - m);
    v1.x = __expf(v1.x - m); v1.y = __expf(v1.y - m);
    v1.z = __expf(v1.z - m); v1.w = __expf(v1.w - m);

    float s = v0.x + v0.y + v0.z + v0.w + v1.x + v1.y + v1.z + v1.w;
    s = warpRedSum(s);
    if ((t & 31) == 0) red[t >> 5] = s;
    __syncthreads();
    s = red[0];
    #pragma unroll
    for (int i = 1; i < 8; i++) s += red[i];

    const float inv = 1.0f / s;
    v0.x *= inv; v0.y *= inv; v0.z *= inv; v0.w *= inv;
    v1.x *= inv; v1.y *= inv; v1.z *= inv; v1.w *= inv;
    p4[t] = v0; p4[t + 256] = v1;

    *(__half2*)&pr[ilv16(k0)]     = __floats2half2_rn(v0.x, v0.y);
    *(__half2*)&pr[ilv16(k0 + 2)] = __floats2half2_rn(v0.z, v0.w);
    *(__half2*)&pr[ilv16(k1)]     = __floats2half2_rn(v1.x, v1.y);
    *(__half2*)&pr[ilv16(k1 + 2)] = __floats2half2_rn(v1.z, v1.w);
}

// ---------------------------------------------------------------------------
extern "C" void kernel_launch(void* const* d_in, const int* in_sizes, int n_in,
                              void* d_out, int out_size)
{
    const float* key   = (const float*)d_in[0];
    const float* query = (const float*)d_in[1];
    const int*   mask  = (const int*)  d_in[2];
    const float* Wq    = (const float*)d_in[3];
    const float* bq    = (const float*)d_in[4];
    const float* Wk    = (const float*)d_in[5];
    const float* bk    = (const float*)d_in[6];
    const float* Wv    = (const float*)d_in[7];
    const float* bv    = (const float*)d_in[8];

    float* out   = (float*)d_out;
    float* score = out + (long)NB * SQL * HIDN;

    __half *xq, *xk, *w, *q, *k, *v, *vt, *p;
    cudaGetSymbolAddress((void**)&xq, g_xq);
    cudaGetSymbolAddress((void**)&xk, g_xk);
    cudaGetSymbolAddress((void**)&w,  g_w);
    cudaGetSymbolAddress((void**)&q,  g_q);
    cudaGetSymbolAddress((void**)&k,  g_k);
    cudaGetSymbolAddress((void**)&v,  g_v);
    cudaGetSymbolAddress((void**)&vt, g_vt);
    cudaGetSymbolAddress((void**)&p,  g_p);

    const int SMEM = 3 * 32768;   // 96KB
    cudaFuncSetAttribute((const void*)proj3,
                         cudaFuncAttributeMaxDynamicSharedMemorySize, SMEM);
    cudaFuncSetAttribute((const void*)hgemm<2, HIDN, SKL>,
                         cudaFuncAttributeMaxDynamicSharedMemorySize, SMEM);
    cudaFuncSetAttribute((const void*)hgemm<3, SKL, HIDN>,
                         cudaFuncAttributeMaxDynamicSharedMemorySize, SMEM);

    dim3 blk(256);

    // fp16 conversions (interleaved-16 along K), fused launches
    const long nbqk = (long)NB * SQL * HIDN / 16;   // 524288 blocks
    const long nbw  = (long)HIDN * HIDN / 16;       // 65536
    dim3 gqk((unsigned)((nbqk + 255) / 256), 1, 2);
    dim3 gw ((unsigned)((nbw + 255) / 256), 1, 3);
    f2h_qk<<<gqk, blk>>>(query, key, xq, xk, nbqk);
    f2h_w <<<gw,  blk>>>(Wq, Wk, Wv, w, nbw);

    // Fused QKV projections: one launch, z in {q/32, k, v}
    dim3 gp(HIDN / 128, (NB * SQL) / 128, 3);
    proj3<<<gp, blk, SMEM>>>(xq, xk, w, bq, bk, bv, q, k, v);

    // V transpose: v[b][sk][h] -> vt[b][h][sk] (interleaved along sk)
    dim3 gt(HIDN / 64, SKL / 64, NB);
    vtrans_k<<<gt, blk>>>(v, vt);

    // Scores: per batch S = (q/32) K^T, mask -> -inf   (fp32 out)
    dim3 gs(SKL / 128, SQL / 128, NB);
    hgemm<2, HIDN, SKL><<<gs, blk, SMEM>>>(q, k, mask, score,
                                           (long)SQL * HIDN, (long)SKL * HIDN,
                                           (long)SQL * SKL);

    // Softmax in place + interleaved fp16 copy to g_p
    softmax_k<<<NB * SQL, 256>>>(score, p);

    // Output: per batch O = P @ V  (NT vs vt[b][h][sk])   fp32 out
    dim3 go(HIDN / 128, SQL / 128, NB);
    hgemm<3, SKL, HIDN><<<go, blk, SMEM>>>(p, vt, nullptr, out,
                                           (long)SQL * SKL, (long)HIDN * SKL,
                                           (long)SQL * HIDN);
}

// round 12
// speedup vs baseline: 1.0385x; 1.0065x over previous
#include <cuda_runtime.h>
#include <cuda_fp16.h>
#include <cstdint>

#define NB   8
#define SQL  2048
#define SKL  2048
#define HIDN 1024
// NORM = 32 -> alpha = 1/32 (folded into q projection; exact in fp16)

// Scratch (__device__ globals per allocation-free rule). All fp16 GEMM
// operands live in "interleaved-16" layout along their K dimension:
// within each 16-half block, halves are stored [0,1,8,9,2,3,10,11,4,5,12,13,6,7,14,15]
// so that mma.m16n8k16 fragments are contiguous 8B chunks in smem.
__device__ __align__(16) __half g_xq[(size_t)NB * SQL * HIDN];  // query fp16 (ilv)
__device__ __align__(16) __half g_xk[(size_t)NB * SKL * HIDN];  // key   fp16 (ilv)
__device__ __align__(16) __half g_w [(size_t)3 * HIDN * HIDN];  // Wq|Wk|Wv fp16 (ilv)
__device__ __align__(16) __half g_q [(size_t)NB * SQL * HIDN];  // q/32 fp16 (ilv)
__device__ __align__(16) __half g_k [(size_t)NB * SKL * HIDN];  // k fp16 (ilv)
__device__ __align__(16) __half g_vt[(size_t)NB * HIDN * SKL];  // v^T [b][h][sk] fp16 (ilv)
__device__ __align__(16) __half g_p [(size_t)NB * SQL * SKL];   // probs fp16 (ilv)

// logical half index -> physical half index (interleave within 16-block)
__device__ __forceinline__ int ilv16(int k) {
    const int blk = k >> 4, kk = k & 15;
    const int p = kk >> 1, lo = kk & 1;
    const int w = (p < 4) ? (2 * p) : (2 * (p - 4) + 1);
    return blk * 16 + 2 * w + lo;
}

__device__ __forceinline__ void mma16(float* c, unsigned a0, unsigned a1,
                                      unsigned a2, unsigned a3,
                                      unsigned b0, unsigned b1) {
    asm volatile(
        "mma.sync.aligned.m16n8k16.row.col.f32.f16.f16.f32 "
        "{%0,%1,%2,%3}, {%4,%5,%6,%7}, {%8,%9}, {%0,%1,%2,%3};\n"
        : "+f"(c[0]), "+f"(c[1]), "+f"(c[2]), "+f"(c[3])
        : "r"(a0), "r"(a1), "r"(a2), "r"(a3), "r"(b0), "r"(b1));
}

__device__ __forceinline__ void cpa16(void* dst, const void* src) {
    unsigned d = (unsigned)__cvta_generic_to_shared(dst);
    asm volatile("cp.async.cg.shared.global [%0], [%1], 16;" :: "r"(d), "l"(src) : "memory");
}
__device__ __forceinline__ void cp_commit() { asm volatile("cp.async.commit_group;"); }
__device__ __forceinline__ void cp_wait1()  { asm volatile("cp.async.wait_group 1;"); }
__device__ __forceinline__ void cp_wait0()  { asm volatile("cp.async.wait_group 0;"); }

// ---------------------------------------------------------------------------
// GEMM core: C[m,n] = sum_k A[m,k]*B[n,k]; A,B fp16 interleaved-16 layout.
// 128x128 CTA tile, BK=64 per sync (four independent 16-K sub-tiles, proven
// 128x16 / 32B-row smem layout each). 8 warps, warp tile 32x64.
// 3-stage cp.async ring (3 x 32KB dynamic smem), rotating stage index
// (PROVEN R7 loop), 1 syncthreads per 64-K iteration. K,N compile-time.
//   MODE 0: C(half) = half((acc + bias[n]) * alpha); il!=0 -> ilv col store
//   MODE 2: C(f32)  = acc; mask==0 -> -inf   (alpha pre-folded into A)
//   MODE 3: C(f32)  = acc
//   MODE 4: vt[b][h][sk] = half(acc + bias[n]) transposed via smem, ilv16 sk
// ---------------------------------------------------------------------------
template<int MODE, int K, int N>
__device__ __forceinline__ void gemm_core(
    const __half* __restrict__ A, const __half* __restrict__ B,
    const float* __restrict__ bias, const int* __restrict__ mask,
    void* __restrict__ Cout, float alpha, int il)
{
    extern __shared__ __align__(16) char sm[];   // 3 stages x [A 16KB | B 16KB]

    const int m0 = blockIdx.y * 128, n0 = blockIdx.x * 128;
    const int t = threadIdx.x, lane = t & 31, warp = t >> 5;
    const int wm = (warp & 3) * 32, wn = (warp >> 2) * 64;
    const int g = lane >> 2, tg = lane & 3;

    // producer mapping: thread -> row (t>>1); lane-pairs cover one aligned
    // 32B sector per cp.async instruction.
    const int prow = t >> 1, ph = t & 1;
    const __half* pA = A + (long)(m0 + prow) * K + ph * 8;
    const __half* pB = B + (long)(n0 + prow) * K + ph * 8;
    const int soff = prow * 32 + ph * 16;     // bytes within a 4KB sub-tile

    float acc[2][8][4];
    #pragma unroll
    for (int i = 0; i < 2; i++)
        #pragma unroll
        for (int j = 0; j < 8; j++)
            #pragma unroll
            for (int l = 0; l < 4; l++) acc[i][j][l] = 0.f;

    auto load_stage = [&](int st, int kt) {   // kt indexes 64-K stages
        char* base = sm + st * 32768;
        const long ko = (long)kt * 64;
        #pragma unroll
        for (int s = 0; s < 4; s++) {         // sub-tile s covers k [16s,16s+16)
            cpa16(base +         s * 4096 + soff, pA + ko + s * 16);
            cpa16(base + 16384 + s * 4096 + soff, pB + ko + s * 16);
        }
    };
    auto comp16 = [&](const char* As, const char* Bs) {
        uint2 bf[8];
        #pragma unroll
        for (int nt = 0; nt < 8; nt++)
            bf[nt] = *(const uint2*)(Bs + (wn + nt * 8 + g) * 32 + tg * 8);
        #pragma unroll
        for (int mt = 0; mt < 2; mt++) {
            const int r = wm + mt * 16 + g;
            const uint2 pa = *(const uint2*)(As + r * 32 + tg * 8);
            const uint2 pb = *(const uint2*)(As + (r + 8) * 32 + tg * 8);
            #pragma unroll
            for (int nt = 0; nt < 8; nt++)
                mma16(acc[mt][nt], pa.x, pb.x, pa.y, pb.y, bf[nt].x, bf[nt].y);
        }
    };
    auto comp = [&](int st) {
        const char* base = sm + st * 32768;
        #pragma unroll
        for (int s = 0; s < 4; s++)
            comp16(base + s * 4096, base + 16384 + s * 4096);
    };

    constexpr int nK = K >> 6;                // 64-K stages (16 or 32)
    load_stage(0, 0); cp_commit();
    load_stage(1, 1); cp_commit();
    cp_wait1();
    __syncthreads();

    int st = 0;
    for (int kt = 0; kt < nK; kt++) {
        comp(st);
        if (kt + 2 < nK) {
            int st2 = st + 2; if (st2 >= 3) st2 -= 3;
            load_stage(st2, kt + 2);
            cp_commit();
            cp_wait1();
        } else {
            cp_wait0();
        }
        __syncthreads();
        if (++st == 3) st = 0;
    }

    // ---------------- epilogues ----------------
    const float NEG = __int_as_float(0xff800000);
    if (MODE == 4) {
        // transposed store to vt via smem (mainloop smem is dead now).
        // Validated numerically in R10 (rel_err bit-identical).
        __half* T = (__half*)sm;
        constexpr int LDT = 138;              // halves per row; conflict-tuned
        #pragma unroll
        for (int mt = 0; mt < 2; mt++) {
            #pragma unroll
            for (int nt = 0; nt < 8; nt++) {
                const int rl = wm + mt * 16 + g;      // local row (sk)
                const int cl = wn + nt * 8 + tg * 2;  // local col (h)
                const float2 bb = *(const float2*)&bias[n0 + cl];
                float* c = acc[mt][nt];
                T[(cl    ) * LDT + rl    ] = __float2half_rn(c[0] + bb.x);
                T[(cl + 1) * LDT + rl    ] = __float2half_rn(c[1] + bb.y);
                T[(cl    ) * LDT + rl + 8] = __float2half_rn(c[2] + bb.x);
                T[(cl + 1) * LDT + rl + 8] = __float2half_rn(c[3] + bb.y);
            }
        }
        __syncthreads();
        const int b_  = m0 >> 11;             // batch  (M rows = b*2048 + sk)
        const int sk0 = m0 & 2047;
        const int hl  = t >> 1;               // local h row 0..127
        const int seg = (t & 1) * 64;         // half of the 128-sk row
        __half* dst = (__half*)Cout + ((long)b_ * HIDN + n0 + hl) * SKL + sk0 + seg;
        const __half* src = T + hl * LDT + seg;
        #pragma unroll
        for (int bk = 0; bk < 4; bk++) {      // 4 x 16-half blocks
            const unsigned* s = (const unsigned*)(src + bk * 16);
            const uint4 w0 = make_uint4(s[0], s[4], s[1], s[5]);  // ilv16 word order
            const uint4 w1 = make_uint4(s[2], s[6], s[3], s[7]);
            ((uint4*)dst)[bk * 2    ] = w0;
            ((uint4*)dst)[bk * 2 + 1] = w1;
        }
        return;
    }

    #pragma unroll
    for (int mt = 0; mt < 2; mt++) {
        #pragma unroll
        for (int nt = 0; nt < 8; nt++) {
            const int row = m0 + wm + mt * 16 + g;
            const int col = n0 + wn + nt * 8 + tg * 2;
            float* c = acc[mt][nt];
            if (MODE == 0) {
                __half* C = (__half*)Cout;
                const float2 bb = *(const float2*)&bias[col];
                const __half2 h0 = __floats2half2_rn((c[0] + bb.x) * alpha,
                                                     (c[1] + bb.y) * alpha);
                const __half2 h1 = __floats2half2_rn((c[2] + bb.x) * alpha,
                                                     (c[3] + bb.y) * alpha);
                const int cc = il ? ilv16(col) : col;
                *(__half2*)&C[(long)row       * N + cc] = h0;
                *(__half2*)&C[(long)(row + 8) * N + cc] = h1;
            } else if (MODE == 2) {
                float* C = (float*)Cout;
                const long r0 = (long)row * N + col;
                const long r1 = (long)(row + 8) * N + col;
                const int2 mv0 = *(const int2*)&mask[r0];
                const int2 mv1 = *(const int2*)&mask[r1];
                *(float2*)&C[r0] = make_float2(mv0.x ? c[0] : NEG, mv0.y ? c[1] : NEG);
                *(float2*)&C[r1] = make_float2(mv1.x ? c[2] : NEG, mv1.y ? c[3] : NEG);
            } else {
                float* C = (float*)Cout;
                *(float2*)&C[(long)row       * N + col] = make_float2(c[0], c[1]);
                *(float2*)&C[(long)(row + 8) * N + col] = make_float2(c[2], c[3]);
            }
        }
    }
}

// Batched fp32-out GEMM (score MODE 2 / output MODE 3), z = batch.
template<int MODE, int K, int N>
__launch_bounds__(256, 2)
__global__ void hgemm(const __half* __restrict__ Ag, const __half* __restrict__ Bg,
                      const int* __restrict__ mask, float* __restrict__ Cg,
                      long sA, long sB, long sC)
{
    const int bz = blockIdx.z;
    gemm_core<MODE, K, N>(Ag + (long)bz * sA, Bg + (long)bz * sB, nullptr,
                          (MODE == 2) ? (mask + (long)bz * sC) : nullptr,
                          Cg + (long)bz * sC, 1.0f, 0);
}

// Fused QKV projection: z=0 -> q/32 (ilv), z=1 -> k (ilv), z=2 -> vt (transposed).
__launch_bounds__(256, 2)
__global__ void proj3(const __half* __restrict__ xq, const __half* __restrict__ xk,
                      const __half* __restrict__ w,
                      const float* __restrict__ bq, const float* __restrict__ bk,
                      const float* __restrict__ bv,
                      __half* __restrict__ q, __half* __restrict__ k,
                      __half* __restrict__ vt)
{
    const int z = blockIdx.z;
    if (z == 0)
        gemm_core<0, HIDN, HIDN>(xq, w, bq, nullptr, q, 0.03125f, 1);
    else if (z == 1)
        gemm_core<0, HIDN, HIDN>(xk, w + (long)HIDN * HIDN, bk, nullptr, k, 1.0f, 1);
    else
        gemm_core<4, HIDN, HIDN>(xk, w + 2L * HIDN * HIDN, bv, nullptr, vt, 1.0f, 0);
}

// ---------------------------------------------------------------------------
// fp32 -> fp16 with interleave-16 permutation. One thread per 16-half block.
// ---------------------------------------------------------------------------
__device__ __forceinline__ void f2h_blk(const float* __restrict__ in,
                                        __half* __restrict__ outp, long i)
{
    const float4 f0 = ((const float4*)in)[i * 4 + 0];
    const float4 f1 = ((const float4*)in)[i * 4 + 1];
    const float4 f2 = ((const float4*)in)[i * 4 + 2];
    const float4 f3 = ((const float4*)in)[i * 4 + 3];
    // phys word order: k(0,1) k(8,9) k(2,3) k(10,11) k(4,5) k(12,13) k(6,7) k(14,15)
    __half2 w[8];
    w[0] = __floats2half2_rn(f0.x, f0.y);
    w[1] = __floats2half2_rn(f2.x, f2.y);
    w[2] = __floats2half2_rn(f0.z, f0.w);
    w[3] = __floats2half2_rn(f2.z, f2.w);
    w[4] = __floats2half2_rn(f1.x, f1.y);
    w[5] = __floats2half2_rn(f3.x, f3.y);
    w[6] = __floats2half2_rn(f1.z, f1.w);
    w[7] = __floats2half2_rn(f3.z, f3.w);
    uint4* dst = (uint4*)(outp + i * 16);
    dst[0] = *(uint4*)&w[0];
    dst[1] = *(uint4*)&w[4];
}

// query+key fused convert: z=0 -> query->xq, z=1 -> key->xk
__global__ void f2h_qk(const float* __restrict__ query, const float* __restrict__ key,
                       __half* __restrict__ xq, __half* __restrict__ xk, long nblk)
{
    const long i = blockIdx.x * (long)blockDim.x + threadIdx.x;
    if (i >= nblk) return;
    if (blockIdx.z == 0) f2h_blk(query, xq, i);
    else                 f2h_blk(key,   xk, i);
}

// 3-weight fused convert: z selects Wq/Wk/Wv -> w + z*H*H
__global__ void f2h_w(const float* __restrict__ Wq, const float* __restrict__ Wk,
                      const float* __restrict__ Wv, __half* __restrict__ w, long nblk)
{
    const long i = blockIdx.x * (long)blockDim.x + threadIdx.x;
    if (i >= nblk) return;
    const int z = blockIdx.z;
    const float* in = (z == 0) ? Wq : (z == 1) ? Wk : Wv;
    f2h_blk(in, w + (long)z * HIDN * HIDN, i);
}

// ---------------------------------------------------------------------------
// Row softmax over SK=2048; -inf mask; fully-masked row -> zeros.
// In-place fp32 S + interleaved fp16 copy P.
// ---------------------------------------------------------------------------
__device__ __forceinline__ float warpRedMax(float v) {
    #pragma unroll
    for (int o = 16; o > 0; o >>= 1) v = fmaxf(v, __shfl_xor_sync(0xffffffffu, v, o));
    return v;
}
__device__ __forceinline__ float warpRedSum(float v) {
    #pragma unroll
    for (int o = 16; o > 0; o >>= 1) v += __shfl_xor_sync(0xffffffffu, v, o);
    return v;
}

__global__ void softmax_k(float* __restrict__ S, __half* __restrict__ P) {
    const long row = blockIdx.x;
    float4* p4 = (float4*)(S + row * (long)SKL);
    __half* pr = P + row * (long)SKL;
    const int t = threadIdx.x;
    __shared__ float red[8];

    float4 v0 = p4[t], v1 = p4[t + 256];
    float m = fmaxf(fmaxf(fmaxf(v0.x, v0.y), fmaxf(v0.z, v0.w)),
                    fmaxf(fmaxf(v1.x, v1.y), fmaxf(v1.z, v1.w)));
    m = warpRedMax(m);
    if ((t & 31) == 0) red[t >> 5] = m;
    __syncthreads();
    m = red[0];
    #pragma unroll
    for (int i = 1; i < 8; i++) m = fmaxf(m, red[i]);
    __syncthreads();

    const int k0 = t * 4, k1 = 1024 + t * 4;
    if (m == __int_as_float(0xff800000)) {
        const float4 z = make_float4(0.f, 0.f, 0.f, 0.f);
        p4[t] = z; p4[t + 256] = z;
        const __half2 hz = __floats2half2_rn(0.f, 0.f);
        *(__half2*)&pr[ilv16(k0)]     = hz;
        *(__half2*)&pr[ilv16(k0 + 2)] = hz;
        *(__half2*)&pr[ilv16(k1)]     = hz;
        *(__half2*)&pr[ilv16(k1 + 2)] = hz;
        return;
    }

    v0.x = __expf(v0.x - m); v0.y = __expf(v0.y - m);
    v0.z = __expf(v0.z - m); v0.w = __expf(v0.w - m);
    v1.x = __expf(v1.x - m); v1.y = __expf(v1.y - m);
    v1.z = __expf(v1.z - m); v1.w = __expf(v1.w - m);

    float s = v0.x + v0.y + v0.z + v0.w + v1.x + v1.y + v1.z + v1.w;
    s = warpRedSum(s);
    if ((t & 31) == 0) red[t >> 5] = s;
    __syncthreads();
    s = red[0];
    #pragma unroll
    for (int i = 1; i < 8; i++) s += red[i];

    const float inv = 1.0f / s;
    v0.x *= inv; v0.y *= inv; v0.z *= inv; v0.w *= inv;
    v1.x *= inv; v1.y *= inv; v1.z *= inv; v1.w *= inv;
    p4[t] = v0; p4[t + 256] = v1;

    *(__half2*)&pr[ilv16(k0)]     = __floats2half2_rn(v0.x, v0.y);
    *(__half2*)&pr[ilv16(k0 + 2)] = __floats2half2_rn(v0.z, v0.w);
    *(__half2*)&pr[ilv16(k1)]     = __floats2half2_rn(v1.x, v1.y);
    *(__half2*)&pr[ilv16(k1 + 2)] = __floats2half2_rn(v1.z, v1.w);
}

// ---------------------------------------------------------------------------
extern "C" void kernel_launch(void* const* d_in, const int* in_sizes, int n_in,
                              void* d_out, int out_size)
{
    const float* key   = (const float*)d_in[0];
    const float* query = (const float*)d_in[1];
    const int*   mask  = (const int*)  d_in[2];
    const float* Wq    = (const float*)d_in[3];
    const float* bq    = (const float*)d_in[4];
    const float* Wk    = (const float*)d_in[5];
    const float* bk    = (const float*)d_in[6];
    const float* Wv    = (const float*)d_in[7];
    const float* bv    = (const float*)d_in[8];

    float* out   = (float*)d_out;
    float* score = out + (long)NB * SQL * HIDN;

    __half *xq, *xk, *w, *q, *k, *vt, *p;
    cudaGetSymbolAddress((void**)&xq, g_xq);
    cudaGetSymbolAddress((void**)&xk, g_xk);
    cudaGetSymbolAddress((void**)&w,  g_w);
    cudaGetSymbolAddress((void**)&q,  g_q);
    cudaGetSymbolAddress((void**)&k,  g_k);
    cudaGetSymbolAddress((void**)&vt, g_vt);
    cudaGetSymbolAddress((void**)&p,  g_p);

    const int SMEM = 3 * 32768;   // 96KB
    cudaFuncSetAttribute((const void*)proj3,
                         cudaFuncAttributeMaxDynamicSharedMemorySize, SMEM);
    cudaFuncSetAttribute((const void*)hgemm<2, HIDN, SKL>,
                         cudaFuncAttributeMaxDynamicSharedMemorySize, SMEM);
    cudaFuncSetAttribute((const void*)hgemm<3, SKL, HIDN>,
                         cudaFuncAttributeMaxDynamicSharedMemorySize, SMEM);

    dim3 blk(256);

    // fp16 conversions (interleaved-16 along K), fused launches
    const long nbqk = (long)NB * SQL * HIDN / 16;   // 524288 blocks
    const long nbw  = (long)HIDN * HIDN / 16;       // 65536
    dim3 gqk((unsigned)((nbqk + 255) / 256), 1, 2);
    dim3 gw ((unsigned)((nbw + 255) / 256), 1, 3);
    f2h_qk<<<gqk, blk>>>(query, key, xq, xk, nbqk);
    f2h_w <<<gw,  blk>>>(Wq, Wk, Wv, w, nbw);

    // Fused QKV projections: one launch, z in {q/32, k, vt(transposed)}
    dim3 gp(HIDN / 128, (NB * SQL) / 128, 3);
    proj3<<<gp, blk, SMEM>>>(xq, xk, w, bq, bk, bv, q, k, vt);

    // Scores: per batch S = (q/32) K^T, mask -> -inf   (fp32 out)
    dim3 gs(SKL / 128, SQL / 128, NB);
    hgemm<2, HIDN, SKL><<<gs, blk, SMEM>>>(q, k, mask, score,
                                           (long)SQL * HIDN, (long)SKL * HIDN,
                                           (long)SQL * SKL);

    // Softmax in place + interleaved fp16 copy to g_p
    softmax_k<<<NB * SQL, 256>>>(score, p);

    // Output: per batch O = P @ V  (NT vs vt[b][h][sk])   fp32 out
    dim3 go(HIDN / 128, SQL / 128, NB);
    hgemm<3, SKL, HIDN><<<go, blk, SMEM>>>(p, vt, nullptr, out,
                                           (long)SQL * SKL, (long)HIDN * SKL,
                                           (long)SQL * HIDN);
}

// round 13
// speedup vs baseline: 1.0899x; 1.0495x over previous
#include <cuda_runtime.h>
#include <cuda_fp16.h>
#include <cstdint>

#define NB   8
#define SQL  2048
#define SKL  2048
#define HIDN 1024
// NORM = 32 -> alpha = 1/32 (folded into q projection; exact in fp16)

// Scratch (__device__ globals per allocation-free rule). All fp16 GEMM
// operands live in "interleaved-32" layout along their K dimension: each
// 32-half block (two 16-K mma sub-tiles) is stored as 4 16B chunks; chunk tg
// = [frag(sub0,tg) 8B | frag(sub1,tg) 8B], where frag(s,tg) = halves
// {16s+2tg, 16s+2tg+1, 16s+2tg+8, 16s+2tg+9}. One LDS.128 in the GEMM
// fetches a thread's fragment for TWO k-subtiles at once.
__device__ __align__(16) __half g_xq[(size_t)NB * SQL * HIDN];  // query fp16 (ilv32)
__device__ __align__(16) __half g_xk[(size_t)NB * SKL * HIDN];  // key   fp16 (ilv32)
__device__ __align__(16) __half g_w [(size_t)3 * HIDN * HIDN];  // Wq|Wk|Wv fp16 (ilv32)
__device__ __align__(16) __half g_q [(size_t)NB * SQL * HIDN];  // q/32 fp16 (ilv32)
__device__ __align__(16) __half g_k [(size_t)NB * SKL * HIDN];  // k fp16 (ilv32)
__device__ __align__(16) __half g_vt[(size_t)NB * HIDN * SKL];  // v^T [b][h][sk] fp16 (ilv32)
__device__ __align__(16) __half g_p [(size_t)NB * SQL * SKL];   // probs fp16 (ilv32)

// logical half index -> physical half index (interleave within 32-block)
__device__ __forceinline__ int ilv32(int k) {
    const int blk = k >> 5, kk = k & 31;
    const int s  = kk >> 4;          // sub-tile 0/1
    const int r  = kk & 15;
    const int tg = (r >> 1) & 3;     // fragment owner
    const int hi = r >> 3, lo = r & 1;
    return blk * 32 + tg * 8 + s * 4 + hi * 2 + lo;
}

__device__ __forceinline__ void mma16(float* c, unsigned a0, unsigned a1,
                                      unsigned a2, unsigned a3,
                                      unsigned b0, unsigned b1) {
    asm volatile(
        "mma.sync.aligned.m16n8k16.row.col.f32.f16.f16.f32 "
        "{%0,%1,%2,%3}, {%4,%5,%6,%7}, {%8,%9}, {%0,%1,%2,%3};\n"
        : "+f"(c[0]), "+f"(c[1]), "+f"(c[2]), "+f"(c[3])
        : "r"(a0), "r"(a1), "r"(a2), "r"(a3), "r"(b0), "r"(b1));
}

__device__ __forceinline__ void cpa16(void* dst, const void* src) {
    unsigned d = (unsigned)__cvta_generic_to_shared(dst);
    asm volatile("cp.async.cg.shared.global [%0], [%1], 16;" :: "r"(d), "l"(src) : "memory");
}
__device__ __forceinline__ void cp_commit() { asm volatile("cp.async.commit_group;"); }
__device__ __forceinline__ void cp_wait1()  { asm volatile("cp.async.wait_group 1;"); }
__device__ __forceinline__ void cp_wait0()  { asm volatile("cp.async.wait_group 0;"); }

// ---------------------------------------------------------------------------
// GEMM core: C[m,n] = sum_k A[m,k]*B[n,k]; A,B fp16 interleaved-32 layout.
// 128x128 CTA tile, BK=64 per sync = two 32-K pairs; smem rows of 64B per
// pair (chunk tg at row*64 + tg*16). 8 warps, warp tile 32x64.
// Fragments via LDS.128 (both sub-tiles of a pair per load).
// 3-stage cp.async ring (3 x 32KB dynamic smem), rotating stage index,
// 1 syncthreads per 64-K iteration. K,N compile-time.
//   MODE 0: C(half) = half((acc + bias[n]) * alpha); il!=0 -> ilv col store
//   MODE 2: C(f32)  = acc; mask==0 -> -inf   (alpha pre-folded into A)
//   MODE 3: C(f32)  = acc
//   MODE 4: vt[b][h][sk] = half(acc + bias[n]) transposed via smem, ilv32 sk
// ---------------------------------------------------------------------------
template<int MODE, int K, int N>
__device__ __forceinline__ void gemm_core(
    const __half* __restrict__ A, const __half* __restrict__ B,
    const float* __restrict__ bias, const int* __restrict__ mask,
    void* __restrict__ Cout, float alpha, int il)
{
    extern __shared__ __align__(16) char sm[];   // 3 stages x [A 16KB | B 16KB]

    const int m0 = blockIdx.y * 128, n0 = blockIdx.x * 128;
    const int t = threadIdx.x, lane = t & 31, warp = t >> 5;
    const int wm = (warp & 3) * 32, wn = (warp >> 2) * 64;
    const int g = lane >> 2, tg = lane & 3;

    // producer mapping: thread -> row (t>>1), ph = t&1; chunk index tg2=ph+2c
    // keeps lane-pairs on one full 32B gmem sector per cp.async instruction.
    const int prow = t >> 1, ph = t & 1;
    const __half* pA = A + (long)(m0 + prow) * K;
    const __half* pB = B + (long)(n0 + prow) * K;

    float acc[2][8][4];
    #pragma unroll
    for (int i = 0; i < 2; i++)
        #pragma unroll
        for (int j = 0; j < 8; j++)
            #pragma unroll
            for (int l = 0; l < 4; l++) acc[i][j][l] = 0.f;

    auto load_stage = [&](int st, int kt) {   // kt indexes 64-K stages
        char* base = sm + st * 32768;
        const long ko = (long)kt * 64;
        #pragma unroll
        for (int p = 0; p < 2; p++) {         // 32-K pair
            #pragma unroll
            for (int c = 0; c < 2; c++) {
                const int tg2 = ph + 2 * c;
                cpa16(base +         p * 8192 + prow * 64 + tg2 * 16,
                      pA + ko + p * 32 + tg2 * 8);
                cpa16(base + 16384 + p * 8192 + prow * 64 + tg2 * 16,
                      pB + ko + p * 32 + tg2 * 8);
            }
        }
    };
    auto comp_pair = [&](const char* Ap, const char* Bp) {   // one 32-K pair
        uint4 bf[8];
        #pragma unroll
        for (int nt = 0; nt < 8; nt++)
            bf[nt] = *(const uint4*)(Bp + (wn + nt * 8 + g) * 64 + tg * 16);
        #pragma unroll
        for (int mt = 0; mt < 2; mt++) {
            const int r = wm + mt * 16 + g;
            const uint4 a0 = *(const uint4*)(Ap + r * 64 + tg * 16);
            const uint4 a1 = *(const uint4*)(Ap + (r + 8) * 64 + tg * 16);
            #pragma unroll
            for (int nt = 0; nt < 8; nt++)     // sub-tile 0
                mma16(acc[mt][nt], a0.x, a1.x, a0.y, a1.y, bf[nt].x, bf[nt].y);
            #pragma unroll
            for (int nt = 0; nt < 8; nt++)     // sub-tile 1
                mma16(acc[mt][nt], a0.z, a1.z, a0.w, a1.w, bf[nt].z, bf[nt].w);
        }
    };
    auto comp = [&](int st) {
        const char* base = sm + st * 32768;
        comp_pair(base,        base + 16384);
        comp_pair(base + 8192, base + 16384 + 8192);
    };

    constexpr int nK = K >> 6;                // 64-K stages (16 or 32)
    load_stage(0, 0); cp_commit();
    load_stage(1, 1); cp_commit();
    cp_wait1();
    __syncthreads();

    int st = 0;
    for (int kt = 0; kt < nK; kt++) {
        comp(st);
        if (kt + 2 < nK) {
            int st2 = st + 2; if (st2 >= 3) st2 -= 3;
            load_stage(st2, kt + 2);
            cp_commit();
            cp_wait1();
        } else {
            cp_wait0();
        }
        __syncthreads();
        if (++st == 3) st = 0;
    }

    // ---------------- epilogues ----------------
    const float NEG = __int_as_float(0xff800000);
    if (MODE == 4) {
        // transposed store to vt via smem (mainloop smem is dead now)
        __half* T = (__half*)sm;
        constexpr int LDT = 138;              // halves per row; conflict-tuned
        #pragma unroll
        for (int mt = 0; mt < 2; mt++) {
            #pragma unroll
            for (int nt = 0; nt < 8; nt++) {
                const int rl = wm + mt * 16 + g;      // local row (sk)
                const int cl = wn + nt * 8 + tg * 2;  // local col (h)
                const float2 bb = *(const float2*)&bias[n0 + cl];
                float* c = acc[mt][nt];
                T[(cl    ) * LDT + rl    ] = __float2half_rn(c[0] + bb.x);
                T[(cl + 1) * LDT + rl    ] = __float2half_rn(c[1] + bb.y);
                T[(cl    ) * LDT + rl + 8] = __float2half_rn(c[2] + bb.x);
                T[(cl + 1) * LDT + rl + 8] = __float2half_rn(c[3] + bb.y);
            }
        }
        __syncthreads();
        const int b_  = m0 >> 11;             // batch  (M rows = b*2048 + sk)
        const int sk0 = m0 & 2047;
        const int hl  = t >> 1;               // local h row 0..127
        const int seg = (t & 1) * 64;         // half of the 128-sk row
        __half* dst = (__half*)Cout + ((long)b_ * HIDN + n0 + hl) * SKL + sk0 + seg;
        const __half* src = T + hl * LDT + seg;
        #pragma unroll
        for (int bk = 0; bk < 2; bk++) {      // 2 x 32-half blocks
            const unsigned* s = (const unsigned*)(src + bk * 32);  // 16 plain words
            #pragma unroll
            for (int c4 = 0; c4 < 4; c4++)    // chunk c4 = words {c4, c4+4, c4+8, c4+12}
                ((uint4*)dst)[bk * 4 + c4] =
                    make_uint4(s[c4], s[c4 + 4], s[c4 + 8], s[c4 + 12]);
        }
        return;
    }

    #pragma unroll
    for (int mt = 0; mt < 2; mt++) {
        #pragma unroll
        for (int nt = 0; nt < 8; nt++) {
            const int row = m0 + wm + mt * 16 + g;
            const int col = n0 + wn + nt * 8 + tg * 2;
            float* c = acc[mt][nt];
            if (MODE == 0) {
                __half* C = (__half*)Cout;
                const float2 bb = *(const float2*)&bias[col];
                const __half2 h0 = __floats2half2_rn((c[0] + bb.x) * alpha,
                                                     (c[1] + bb.y) * alpha);
                const __half2 h1 = __floats2half2_rn((c[2] + bb.x) * alpha,
                                                     (c[3] + bb.y) * alpha);
                const int cc = il ? ilv32(col) : col;
                *(__half2*)&C[(long)row       * N + cc] = h0;
                *(__half2*)&C[(long)(row + 8) * N + cc] = h1;
            } else if (MODE == 2) {
                float* C = (float*)Cout;
                const long r0 = (long)row * N + col;
                const long r1 = (long)(row + 8) * N + col;
                const int2 mv0 = *(const int2*)&mask[r0];
                const int2 mv1 = *(const int2*)&mask[r1];
                *(float2*)&C[r0] = make_float2(mv0.x ? c[0] : NEG, mv0.y ? c[1] : NEG);
                *(float2*)&C[r1] = make_float2(mv1.x ? c[2] : NEG, mv1.y ? c[3] : NEG);
            } else {
                float* C = (float*)Cout;
                *(float2*)&C[(long)row       * N + col] = make_float2(c[0], c[1]);
                *(float2*)&C[(long)(row + 8) * N + col] = make_float2(c[2], c[3]);
            }
        }
    }
}

// Batched fp32-out GEMM (score MODE 2 / output MODE 3), z = batch.
template<int MODE, int K, int N>
__launch_bounds__(256, 2)
__global__ void hgemm(const __half* __restrict__ Ag, const __half* __restrict__ Bg,
                      const int* __restrict__ mask, float* __restrict__ Cg,
                      long sA, long sB, long sC)
{
    const int bz = blockIdx.z;
    gemm_core<MODE, K, N>(Ag + (long)bz * sA, Bg + (long)bz * sB, nullptr,
                          (MODE == 2) ? (mask + (long)bz * sC) : nullptr,
                          Cg + (long)bz * sC, 1.0f, 0);
}

// Fused QKV projection: z=0 -> q/32 (ilv), z=1 -> k (ilv), z=2 -> vt (transposed).
__launch_bounds__(256, 2)
__global__ void proj3(const __half* __restrict__ xq, const __half* __restrict__ xk,
                      const __half* __restrict__ w,
                      const float* __restrict__ bq, const float* __restrict__ bk,
                      const float* __restrict__ bv,
                      __half* __restrict__ q, __half* __restrict__ k,
                      __half* __restrict__ vt)
{
    const int z = blockIdx.z;
    if (z == 0)
        gemm_core<0, HIDN, HIDN>(xq, w, bq, nullptr, q, 0.03125f, 1);
    else if (z == 1)
        gemm_core<0, HIDN, HIDN>(xk, w + (long)HIDN * HIDN, bk, nullptr, k, 1.0f, 1);
    else
        gemm_core<4, HIDN, HIDN>(xk, w + 2L * HIDN * HIDN, bv, nullptr, vt, 1.0f, 0);
}

// ---------------------------------------------------------------------------
// fp32 -> fp16 with interleave-32 permutation. One thread per 32-half block.
// ---------------------------------------------------------------------------
__device__ __forceinline__ void f2h_blk(const float* __restrict__ in,
                                        __half* __restrict__ outp, long i)
{
    float4 f[8];
    #pragma unroll
    for (int j = 0; j < 8; j++) f[j] = ((const float4*)in)[i * 8 + j];
    __half2 h[16];                     // h[p] = halves (k2p, k2p+1)
    #pragma unroll
    for (int j = 0; j < 8; j++) {
        h[2 * j]     = __floats2half2_rn(f[j].x, f[j].y);
        h[2 * j + 1] = __floats2half2_rn(f[j].z, f[j].w);
    }
    uint4* dst = (uint4*)(outp + i * 32);
    #pragma unroll
    for (int c4 = 0; c4 < 4; c4++)     // chunk c4 = (h[c4], h[c4+4], h[c4+8], h[c4+12])
        dst[c4] = make_uint4(*(unsigned*)&h[c4],     *(unsigned*)&h[c4 + 4],
                             *(unsigned*)&h[c4 + 8], *(unsigned*)&h[c4 + 12]);
}

// query+key fused convert: z=0 -> query->xq, z=1 -> key->xk
__global__ void f2h_qk(const float* __restrict__ query, const float* __restrict__ key,
                       __half* __restrict__ xq, __half* __restrict__ xk, long nblk)
{
    const long i = blockIdx.x * (long)blockDim.x + threadIdx.x;
    if (i >= nblk) return;
    if (blockIdx.z == 0) f2h_blk(query, xq, i);
    else                 f2h_blk(key,   xk, i);
}

// 3-weight fused convert: z selects Wq/Wk/Wv -> w + z*H*H
__global__ void f2h_w(const float* __restrict__ Wq, const float* __restrict__ Wk,
                      const float* __restrict__ Wv, __half* __restrict__ w, long nblk)
{
    const long i = blockIdx.x * (long)blockDim.x + threadIdx.x;
    if (i >= nblk) return;
    const int z = blockIdx.z;
    const float* in = (z == 0) ? Wq : (z == 1) ? Wk : Wv;
    f2h_blk(in, w + (long)z * HIDN * HIDN, i);
}

// ---------------------------------------------------------------------------
// Row softmax over SK=2048; -inf mask; fully-masked row -> zeros.
// In-place fp32 S + interleaved fp16 copy P.
// ---------------------------------------------------------------------------
__device__ __forceinline__ float warpRedMax(float v) {
    #pragma unroll
    for (int o = 16; o > 0; o >>= 1) v = fmaxf(v, __shfl_xor_sync(0xffffffffu, v, o));
    return v;
}
__device__ __forceinline__ float warpRedSum(float v) {
    #pragma unroll
    for (int o = 16; o > 0; o >>= 1) v += __shfl_xor_sync(0xffffffffu, v, o);
    return v;
}

__global__ void softmax_k(float* __restrict__ S, __half* __restrict__ P) {
    const long row = blockIdx.x;
    float4* p4 = (float4*)(S + row * (long)SKL);
    __half* pr = P + row * (long)SKL;
    const int t = threadIdx.x;
    __shared__ float red[8];

    float4 v0 = p4[t], v1 = p4[t + 256];
    float m = fmaxf(fmaxf(fmaxf(v0.x, v0.y), fmaxf(v0.z, v0.w)),
                    fmaxf(fmaxf(v1.x, v1.y), fmaxf(v1.z, v1.w)));
    m = warpRedMax(m);
    if ((t & 31) == 0) red[t >> 5] = m;
    __syncthreads();
    m = red[0];
    #pragma unroll
    for (int i = 1; i < 8; i++) m = fmaxf(m, red[i]);
    __syncthreads();

    const int k0 = t * 4, k1 = 1024 + t * 4;
    if (m == __int_as_float(0xff800000)) {
        const float4 z = make_float4(0.f, 0.f, 0.f, 0.f);
        p4[t] = z; p4[t + 256] = z;
        const __half2 hz = __floats2half2_rn(0.f, 0.f);
        *(__half2*)&pr[ilv32(k0)]     = hz;
        *(__half2*)&pr[ilv32(k0 + 2)] = hz;
        *(__half2*)&pr[ilv32(k1)]     = hz;
        *(__half2*)&pr[ilv32(k1 + 2)] = hz;
        return;
    }

    v0.x = __expf(v0.x - m); v0.y = __expf(v0.y - m);
    v0.z = __expf(v0.z - m); v0.w = __expf(v0.w - m);
    v1.x = __expf(v1.x - m); v1.y = __expf(v1.y - m);
    v1.z = __expf(v1.z - m); v1.w = __expf(v1.w - m);

    float s = v0.x + v0.y + v0.z + v0.w + v1.x + v1.y + v1.z + v1.w;
    s = warpRedSum(s);
    if ((t & 31) == 0) red[t >> 5] = s;
    __syncthreads();
    s = red[0];
    #pragma unroll
    for (int i = 1; i < 8; i++) s += red[i];

    const float inv = 1.0f / s;
    v0.x *= inv; v0.y *= inv; v0.z *= inv; v0.w *= inv;
    v1.x *= inv; v1.y *= inv; v1.z *= inv; v1.w *= inv;
    p4[t] = v0; p4[t + 256] = v1;

    *(__half2*)&pr[ilv32(k0)]     = __floats2half2_rn(v0.x, v0.y);
    *(__half2*)&pr[ilv32(k0 + 2)] = __floats2half2_rn(v0.z, v0.w);
    *(__half2*)&pr[ilv32(k1)]     = __floats2half2_rn(v1.x, v1.y);
    *(__half2*)&pr[ilv32(k1 + 2)] = __floats2half2_rn(v1.z, v1.w);
}

// ---------------------------------------------------------------------------
extern "C" void kernel_launch(void* const* d_in, const int* in_sizes, int n_in,
                              void* d_out, int out_size)
{
    const float* key   = (const float*)d_in[0];
    const float* query = (const float*)d_in[1];
    const int*   mask  = (const int*)  d_in[2];
    const float* Wq    = (const float*)d_in[3];
    const float* bq    = (const float*)d_in[4];
    const float* Wk    = (const float*)d_in[5];
    const float* bk    = (const float*)d_in[6];
    const float* Wv    = (const float*)d_in[7];
    const float* bv    = (const float*)d_in[8];

    float* out   = (float*)d_out;
    float* score = out + (long)NB * SQL * HIDN;

    __half *xq, *xk, *w, *q, *k, *vt, *p;
    cudaGetSymbolAddress((void**)&xq, g_xq);
    cudaGetSymbolAddress((void**)&xk, g_xk);
    cudaGetSymbolAddress((void**)&w,  g_w);
    cudaGetSymbolAddress((void**)&q,  g_q);
    cudaGetSymbolAddress((void**)&k,  g_k);
    cudaGetSymbolAddress((void**)&vt, g_vt);
    cudaGetSymbolAddress((void**)&p,  g_p);

    const int SMEM = 3 * 32768;   // 96KB
    cudaFuncSetAttribute((const void*)proj3,
                         cudaFuncAttributeMaxDynamicSharedMemorySize, SMEM);
    cudaFuncSetAttribute((const void*)hgemm<2, HIDN, SKL>,
                         cudaFuncAttributeMaxDynamicSharedMemorySize, SMEM);
    cudaFuncSetAttribute((const void*)hgemm<3, SKL, HIDN>,
                         cudaFuncAttributeMaxDynamicSharedMemorySize, SMEM);

    dim3 blk(256);

    // fp16 conversions (interleaved-32 along K), fused launches
    const long nbqk = (long)NB * SQL * HIDN / 32;   // 524288 blocks
    const long nbw  = (long)HIDN * HIDN / 32;       // 32768
    dim3 gqk((unsigned)((nbqk + 255) / 256), 1, 2);
    dim3 gw ((unsigned)((nbw + 255) / 256), 1, 3);
    f2h_qk<<<gqk, blk>>>(query, key, xq, xk, nbqk);
    f2h_w <<<gw,  blk>>>(Wq, Wk, Wv, w, nbw);

    // Fused QKV projections: one launch, z in {q/32, k, vt(transposed)}
    dim3 gp(HIDN / 128, (NB * SQL) / 128, 3);
    proj3<<<gp, blk, SMEM>>>(xq, xk, w, bq, bk, bv, q, k, vt);

    // Scores: per batch S = (q/32) K^T, mask -> -inf   (fp32 out)
    dim3 gs(SKL / 128, SQL / 128, NB);
    hgemm<2, HIDN, SKL><<<gs, blk, SMEM>>>(q, k, mask, score,
                                           (long)SQL * HIDN, (long)SKL * HIDN,
                                           (long)SQL * SKL);

    // Softmax in place + interleaved fp16 copy to g_p
    softmax_k<<<NB * SQL, 256>>>(score, p);

    // Output: per batch O = P @ V  (NT vs vt[b][h][sk])   fp32 out
    dim3 go(HIDN / 128, SQL / 128, NB);
    hgemm<3, SKL, HIDN><<<go, blk, SMEM>>>(p, vt, nullptr, out,
                                           (long)SQL * SKL, (long)HIDN * SKL,
                                           (long)SQL * HIDN);
}